// round 1
// baseline (speedup 1.0000x reference)
#include <cuda_runtime.h>

typedef unsigned long long ull;

#define TT       30
#define BB       1048576
#define THREADS  256
#define HALF     (BB / 2)

// ---------------- packed f32x2 helpers ----------------
__device__ __forceinline__ ull pk(float lo, float hi) {
    ull r; asm("mov.b64 %0, {%1,%2};" : "=l"(r) : "f"(lo), "f"(hi)); return r;
}
__device__ __forceinline__ void upk(float& lo, float& hi, ull v) {
    asm("mov.b64 {%0,%1}, %2;" : "=f"(lo), "=f"(hi) : "l"(v));
}
__device__ __forceinline__ ull fma2(ull a, ull b, ull c) {
    ull d; asm("fma.rn.f32x2 %0, %1, %2, %3;" : "=l"(d) : "l"(a), "l"(b), "l"(c)); return d;
}
__device__ __forceinline__ ull add2(ull a, ull b) {
    ull d; asm("add.rn.f32x2 %0, %1, %2;" : "=l"(d) : "l"(a), "l"(b)); return d;
}
__device__ __forceinline__ ull relu2(ull v) {
    float a, b; upk(a, b, v);
    return pk(fmaxf(a, 0.0f), fmaxf(b, 0.0f));
}
// tanh(z) = 1 - 2/(exp(2z)+1), exp via MUFU.EX2, division via MUFU.RCP (~1e-6 rel err)
__device__ __forceinline__ float fast_tanh(float z) {
    float e; asm("ex2.approx.f32 %0, %1;" : "=f"(e) : "f"(z * 2.8853900817779268f));
    float r; asm("rcp.approx.f32 %0, %1;" : "=f"(r) : "f"(e + 1.0f));
    return fmaf(-2.0f, r, 1.0f);
}

// Shared layout (floats):
//   sW1 : [0,    1200)   W1  [T][2][20]
//   sB1 : [1200, 1800)   b1  [T][20]
//   sW2 : [1800, 2400)   W2  [T][20]
//   sB2 : [2400, 2432)   b2  [T] (+pad)
//   sIO : [2432, 17792)  x/out staging: 2 regions x 256 elems x 30 floats
#define SMEM_FLOATS 17792

__global__ __launch_bounds__(THREADS, 2)
void rnn_kernel(const float* __restrict__ gx,
                const float* __restrict__ gW1,
                const float* __restrict__ gb1,
                const float* __restrict__ gW2,
                const float* __restrict__ gb2,
                float* __restrict__ gout)
{
    extern __shared__ float smem[];
    float* sW1 = smem;
    float* sB1 = smem + 1200;
    float* sW2 = smem + 1800;
    float* sB2 = smem + 2400;
    float* sIO = smem + 2432;

    const int tid = threadIdx.x;
    const int base0 = blockIdx.x * THREADS;  // element base, region 0

    // ---- stage weights (coalesced float4) ----
    {
        float4*       d = (float4*)sW1;
        const float4* s = (const float4*)gW1;
        for (int i = tid; i < 300; i += THREADS) d[i] = s[i];
        d = (float4*)sB1; s = (const float4*)gb1;
        for (int i = tid; i < 150; i += THREADS) d[i] = s[i];
        d = (float4*)sW2; s = (const float4*)gW2;
        for (int i = tid; i < 150; i += THREADS) d[i] = s[i];
        if (tid < TT) sB2[tid] = gb2[tid];
    }
    // ---- stage x (coalesced float4: per-region 256*30 floats = 1920 float4) ----
    {
        float4*       d  = (float4*)sIO;
        const float4* s0 = (const float4*)(gx + (size_t)base0 * TT);
        const float4* s1 = (const float4*)(gx + (size_t)(base0 + HALF) * TT);
        for (int i = tid; i < 1920; i += THREADS) d[i]        = s0[i];
        for (int i = tid; i < 1920; i += THREADS) d[1920 + i] = s1[i];
    }
    __syncthreads();

    float* io0 = sIO + tid * TT;                // this thread's element (region 0)
    float* io1 = sIO + (THREADS + tid) * TT;    // this thread's element (region 1)

    const ull* w1u = (const ull*)sW1;   // per t: 20 ulls (10 row0 pairs, 10 row1 pairs)
    const ull* b1u = (const ull*)sB1;   // per t: 10 ulls
    const ull* w2u = (const ull*)sW2;   // per t: 10 ulls

    float o0 = 0.0f, o1 = 0.0f;

    #pragma unroll 1
    for (int t = 0; t < TT; ++t) {
        const ulonglong2* w1t = (const ulonglong2*)(w1u + t * 20);
        const ulonglong2* b1t = (const ulonglong2*)(b1u + t * 10);
        const ulonglong2* w2t = (const ulonglong2*)(w2u + t * 10);
        const float bt2 = sB2[t];
        const float x0  = io0[t];
        const float x1  = io1[t];

        ull xx0 = pk(x0, x0), oo0 = pk(o0, o0);
        ull xx1 = pk(x1, x1), oo1 = pk(o1, o1);
        ull accA0 = pk(bt2, 0.0f), accB0 = pk(0.0f, 0.0f);
        ull accA1 = accA0,         accB1 = accB0;

        #pragma unroll
        for (int q = 0; q < 5; ++q) {
            ulonglong2 wa = w1t[q];       // W1 row0, hidden units 4q..4q+3
            ulonglong2 wb = w1t[5 + q];   // W1 row1, hidden units 4q..4q+3
            ulonglong2 bb = b1t[q];       // b1,      hidden units 4q..4q+3
            ulonglong2 w2 = w2t[q];       // W2,      hidden units 4q..4q+3

            ull hA0 = fma2(xx0, wa.x, fma2(oo0, wb.x, bb.x));
            ull hB0 = fma2(xx0, wa.y, fma2(oo0, wb.y, bb.y));
            ull hA1 = fma2(xx1, wa.x, fma2(oo1, wb.x, bb.x));
            ull hB1 = fma2(xx1, wa.y, fma2(oo1, wb.y, bb.y));

            accA0 = fma2(relu2(hA0), w2.x, accA0);
            accB0 = fma2(relu2(hB0), w2.y, accB0);
            accA1 = fma2(relu2(hA1), w2.x, accA1);
            accB1 = fma2(relu2(hB1), w2.y, accB1);
        }
        {
            float a, b;
            upk(a, b, add2(accA0, accB0));
            o0 = fast_tanh(a + b);
            upk(a, b, add2(accA1, accB1));
            o1 = fast_tanh(a + b);
        }
        io0[t] = o0;    // overwrite consumed x slot with output
        io1[t] = o1;
    }

    __syncthreads();

    // ---- writeback (coalesced float4) ----
    {
        const float4* s  = (const float4*)sIO;
        float4*       d0 = (float4*)(gout + (size_t)base0 * TT);
        float4*       d1 = (float4*)(gout + (size_t)(base0 + HALF) * TT);
        for (int i = tid; i < 1920; i += THREADS) d0[i] = s[i];
        for (int i = tid; i < 1920; i += THREADS) d1[i] = s[1920 + i];
    }
}

extern "C" void kernel_launch(void* const* d_in, const int* in_sizes, int n_in,
                              void* d_out, int out_size)
{
    const float* x  = (const float*)d_in[0];
    const float* W1 = (const float*)d_in[1];
    const float* b1 = (const float*)d_in[2];
    const float* W2 = (const float*)d_in[3];
    const float* b2 = (const float*)d_in[4];

    const int smem_bytes = SMEM_FLOATS * (int)sizeof(float);  // 71168
    cudaFuncSetAttribute(rnn_kernel, cudaFuncAttributeMaxDynamicSharedMemorySize, smem_bytes);

    rnn_kernel<<<BB / (2 * THREADS), THREADS, smem_bytes>>>(x, W1, b1, W2, b2, (float*)d_out);
}